// round 2
// baseline (speedup 1.0000x reference)
#include <cuda_runtime.h>
#include <math.h>

#define NPTS 1000000
#define NLEV 12
#define TSZ  524288          // 2^19
#define FDIM 8
#define TOTAL (NPTS * NLEV)

struct Res12 { int r[NLEV]; };

__device__ __forceinline__ float sgnf(float v) {
    // matches jnp.sign: -1, 0, +1 (0 for +-0 and NaN-free inputs)
    return (float)((v > 0.0f) - (v < 0.0f));
}

__global__ __launch_bounds__(256) void hash_enc_kernel(
    const float*  __restrict__ coords,   // [NPTS, 3]
    const float*  __restrict__ tables,   // [NLEV, TSZ, FDIM]
    float*        __restrict__ out,      // [NPTS, NLEV*FDIM]
    Res12 rr)
{
    int t = blockIdx.x * blockDim.x + threadIdx.x;
    if (t >= TOTAL) return;
    int n = t / NLEV;                    // strength-reduced to imad.hi by ptxas
    int l = t - n * NLEV;

    // 12 consecutive threads load the same 3 floats -> L1 broadcast, cheap
    float cx = __ldg(coords + 3 * n + 0);
    float cy = __ldg(coords + 3 * n + 1);
    float cz = __ldg(coords + 3 * n + 2);

    int   res = rr.r[l];                 // constant bank (LDC), warp-uniform-ish
    float rf  = (float)res;              // <=512, exact in f32

    // f32 multiply + floor + clamp: bit-identical to the JAX reference
    // (jax promotes f32 * int -> f32 here, so fp32 math is the exact path)
    int ci0 = (int)floorf(cx * rf); ci0 = min(max(ci0, 0), res - 1);
    int ci1 = (int)floorf(cy * rf); ci1 = min(max(ci1, 0), res - 1);
    int ci2 = (int)floorf(cz * rf); ci2 = min(max(ci2, 0), res - 1);

    // h % 2^19 depends only on the low 32 bits of the int64 products:
    // uint32 wraparound == truncation of the non-negative int64 value.
    unsigned h = (unsigned)ci0
               ^ ((unsigned)ci1 * 2654435761u)
               ^ ((unsigned)ci2 * 805459861u);
    unsigned idx = h & (TSZ - 1);

    // 32B-aligned random gather: exactly two 16B sectors, non-coherent path
    const float4* tp = (const float4*)(tables + ((size_t)l * TSZ + idx) * FDIM);
    float4 a = __ldg(tp);
    float4 b = __ldg(tp + 1);

    float4 sa = make_float4(sgnf(a.x), sgnf(a.y), sgnf(a.z), sgnf(a.w));
    float4 sb = make_float4(sgnf(b.x), sgnf(b.y), sgnf(b.z), sgnf(b.w));

    // warp writes 1KB contiguous; streaming hint keeps the 384MB output
    // stream from evicting hot table lines out of L2
    float4* op = (float4*)(out + (size_t)t * FDIM);   // t*8 == n*96 + l*8
    __stcs(op,     sa);
    __stcs(op + 1, sb);
}

extern "C" void kernel_launch(void* const* d_in, const int* in_sizes, int n_in,
                              void* d_out, int out_size)
{
    // Disambiguate inputs by size: coords = 3e6 elems, tables = 12*2^19*8.
    const float* coords = (const float*)d_in[0];
    const float* tables = (const float*)d_in[1];
    if (n_in >= 2 && in_sizes[0] > in_sizes[1]) {
        coords = (const float*)d_in[1];
        tables = (const float*)d_in[0];
    }
    float* out = (float*)d_out;                    // [1e6, 96] f32

    // mirror numpy: int(16 * (512/16) ** (l/11)) computed in double
    Res12 rr;
    for (int l = 0; l < NLEV; ++l)
        rr.r[l] = (int)(16.0 * pow(32.0, (double)l / 11.0));

    const int threads = 256;
    const int blocks  = (TOTAL + threads - 1) / threads;   // 46875, tail-free
    hash_enc_kernel<<<blocks, threads>>>(coords, tables, out, rr);
}